// round 9
// baseline (speedup 1.0000x reference)
#include <cuda_runtime.h>
#include <cuda_bf16.h>
#include <cuda_fp16.h>
#include <cstdint>

#define BATCH 8
#define NPTS  4096
#define DIM   256            // elements per row (int8: 256 bytes)

// tile geometry
#define TILE_N 256           // X rows per CTA (gemm M)
#define TILE_M 128           // Y rows per CTA (gemm N)
#define KCHB   64            // K bytes per stage
#define NSTG   4             // DIM / KCHB
#define SSTB   80            // smem row stride in bytes (ldmatrix conflict-free)

#define A_ST   (TILE_N * SSTB)             // 20480
#define B_ST   (TILE_M * SSTB)             // 10240
#define STAGE_BYTES (A_ST + B_ST)          // 30720
#define SMEM_BYTES  (4 * STAGE_BYTES)      // 122880

// ---------------- scratch globals ----------------
__device__ unsigned g_min_n[BATCH * NPTS];
__device__ unsigned g_min_m[BATCH * NPTS];
__device__ float    g_xx[BATCH * NPTS];
__device__ float    g_yy[BATCH * NPTS];
__device__ float    g_sx[BATCH * NPTS];    // dequant scale per X row (max/127)
__device__ float    g_sy[BATCH * NPTS];    // dequant scale per Y row
__device__ __align__(128) char g_xq[BATCH * NPTS * DIM];   // 8 MB int8
__device__ __align__(128) char g_yq[BATCH * NPTS * DIM];   // 8 MB int8

__device__ __forceinline__ unsigned f2ord(float f) {
    unsigned u = __float_as_uint(f);
    return (u & 0x80000000u) ? ~u : (u ^ 0x80000000u);
}
__device__ __forceinline__ float ord2f(unsigned u) {
    u = (u & 0x80000000u) ? (u ^ 0x80000000u) : ~u;
    return __uint_as_float(u);
}

__device__ __forceinline__ uint32_t smem_u32(const void* p) {
    uint32_t a;
    asm("{ .reg .u64 t; cvta.to.shared.u64 t, %1; cvt.u32.u64 %0, t; }" : "=r"(a) : "l"(p));
    return a;
}
__device__ __forceinline__ void cpasync16(uint32_t dst, const void* src) {
    asm volatile("cp.async.cg.shared.global [%0], [%1], 16;" :: "r"(dst), "l"(src));
}
#define CP_COMMIT() asm volatile("cp.async.commit_group;" ::: "memory")
template <int N>
__device__ __forceinline__ void cp_wait() {
    asm volatile("cp.async.wait_group %0;" :: "n"(N) : "memory");
}

#define LDSM_X4(r, a) \
    asm volatile("ldmatrix.sync.aligned.m8n8.x4.shared.b16 {%0,%1,%2,%3}, [%4];" \
        : "=r"((r)[0]), "=r"((r)[1]), "=r"((r)[2]), "=r"((r)[3]) : "r"(a))

__device__ __forceinline__ void mma_s8(int& d0, int& d1, int& d2, int& d3,
                                       uint32_t a0, uint32_t a1, uint32_t a2, uint32_t a3,
                                       uint32_t b0, uint32_t b1) {
    asm volatile(
        "mma.sync.aligned.m16n8k32.row.col.s32.s8.s8.s32 "
        "{%0,%1,%2,%3}, {%4,%5,%6,%7}, {%8,%9}, {%0,%1,%2,%3};"
        : "+r"(d0), "+r"(d1), "+r"(d2), "+r"(d3)
        : "r"(a0), "r"(a1), "r"(a2), "r"(a3), "r"(b0), "r"(b1));
}

__device__ __forceinline__ int q8(float x, float inv) {
    int q = __float2int_rn(x * inv);
    return max(-127, min(127, q));
}

// ---------------------------------------------------------------------------
// Kernel 1: row norms + per-row max + int8 quantization + min init
// one warp per row; grid ((B*N)/8, 2), block 256
// ---------------------------------------------------------------------------
__global__ void norms_init_kernel(const float* __restrict__ X,
                                  const float* __restrict__ Y) {
    int warp = (blockIdx.x * blockDim.x + threadIdx.x) >> 5;
    int lane = threadIdx.x & 31;
    const float* src = (blockIdx.y == 0) ? X : Y;
    float*    dst_n  = (blockIdx.y == 0) ? g_xx : g_yy;
    float*    dst_s  = (blockIdx.y == 0) ? g_sx : g_sy;
    unsigned* dst_mn = (blockIdx.y == 0) ? g_min_n : g_min_m;
    char*     dst_q  = (blockIdx.y == 0) ? g_xq : g_yq;

    const float4* row = (const float4*)(src + (size_t)warp * DIM);
    float4 a = row[lane];
    float4 b = row[lane + 32];

    float s = a.x * a.x + a.y * a.y + a.z * a.z + a.w * a.w
            + b.x * b.x + b.y * b.y + b.z * b.z + b.w * b.w;
    float m = fmaxf(fmaxf(fmaxf(fabsf(a.x), fabsf(a.y)), fmaxf(fabsf(a.z), fabsf(a.w))),
                    fmaxf(fmaxf(fabsf(b.x), fabsf(b.y)), fmaxf(fabsf(b.z), fabsf(b.w))));
#pragma unroll
    for (int off = 16; off > 0; off >>= 1) {
        s += __shfl_xor_sync(0xFFFFFFFFu, s, off);
        m = fmaxf(m, __shfl_xor_sync(0xFFFFFFFFu, m, off));
    }
    m = fmaxf(m, 1e-20f);
    const float inv = 127.0f / m;

    uint32_t* qrow = (uint32_t*)(dst_q + (size_t)warp * DIM);
    uint32_t pa = (uint32_t)(q8(a.x, inv) & 0xFF)
                | ((uint32_t)(q8(a.y, inv) & 0xFF) << 8)
                | ((uint32_t)(q8(a.z, inv) & 0xFF) << 16)
                | ((uint32_t)(q8(a.w, inv) & 0xFF) << 24);
    uint32_t pb = (uint32_t)(q8(b.x, inv) & 0xFF)
                | ((uint32_t)(q8(b.y, inv) & 0xFF) << 8)
                | ((uint32_t)(q8(b.z, inv) & 0xFF) << 16)
                | ((uint32_t)(q8(b.w, inv) & 0xFF) << 24);
    qrow[lane]      = pa;
    qrow[lane + 32] = pb;

    if (lane == 0) {
        dst_n[warp]  = s;
        dst_s[warp]  = m * (1.0f / 127.0f);
        dst_mn[warp] = 0xFFFFFFFFu;
    }
}

// ---------------------------------------------------------------------------
// Kernel 2: int8 mma.sync tiles. CTA = 256(n) x 128(m), 512 threads.
// grid: (NPTS/TILE_M, NPTS/TILE_N, BATCH)
// ---------------------------------------------------------------------------
__global__ __launch_bounds__(512, 1)
void chamfer_mma_kernel() {
    extern __shared__ __align__(16) char smem[];
    const uint32_t sb = smem_u32(smem);

    const int tid  = threadIdx.x;
    const int wid  = tid >> 5;
    const int lane = tid & 31;
    const int r4   = lane >> 2;   // 0..7
    const int c4   = lane & 3;    // 0..3
    const int wn   = wid >> 2;    // warp n-group: 64 rows
    const int wm   = wid & 3;     // warp m-group: 32 cols

    const int b  = blockIdx.z;
    const int n0 = blockIdx.y * TILE_N;
    const int m0 = blockIdx.x * TILE_M;

    const char* xb = g_xq + ((size_t)b * NPTS + n0) * DIM;
    const char* yb = g_yq + ((size_t)b * NPTS + m0) * DIM;

    // ldmatrix per-lane base byte offsets within a stage
    const uint32_t a_off = (uint32_t)((wn * 64 + (lane & 15)) * SSTB
                                      + ((lane >> 4) & 1) * 16);
    const uint32_t b_off = (uint32_t)(A_ST
                         + (wm * 32 + (lane >> 4) * 8 + (lane & 7)) * SSTB
                         + ((lane >> 3) & 1) * 16);

    // ---- async load of one K-chunk stage (64 bytes per row) ----
    auto load_stage = [&](int s) {
        const uint32_t base = sb + s * STAGE_BYTES;
        const int koff = s * KCHB;
        // A: 256 rows x 4 x 16B = 1024 chunks
#pragma unroll
        for (int i = 0; i < 2; ++i) {
            int cid = tid + i * 512;
            int row = cid >> 2, c16 = cid & 3;
            cpasync16(base + (uint32_t)(row * SSTB + c16 * 16),
                      xb + (size_t)row * DIM + koff + c16 * 16);
        }
        // B: 128 rows x 4 = 512 chunks
        {
            int row = tid >> 2, c16 = tid & 3;
            cpasync16(base + (uint32_t)(A_ST + row * SSTB + c16 * 16),
                      yb + (size_t)row * DIM + koff + c16 * 16);
        }
        CP_COMMIT();
    };

    // all 4 stages prefetched up front
    load_stage(0); load_stage(1); load_stage(2); load_stage(3);

    int acc[4][4][4];
#pragma unroll
    for (int fi = 0; fi < 4; ++fi)
#pragma unroll
        for (int fj = 0; fj < 4; ++fj)
#pragma unroll
            for (int q = 0; q < 4; ++q) acc[fi][fj][q] = 0;

    auto compute_stage = [&](int s) {
        const uint32_t stage = sb + s * STAGE_BYTES;
        const uint32_t a_base = stage + a_off;
        const uint32_t b_base = stage + b_off;
#pragma unroll
        for (int ks = 0; ks < 2; ++ks) {          // two k32 steps (32 bytes apart)
            const uint32_t kb = ks * 32;
            uint32_t af[4][4], bf0[4], bf1[4];
            LDSM_X4(bf0, b_base + kb);             // fj0:{b0,b1}, fj1:{b0,b1}
            LDSM_X4(bf1, b_base + 16 * SSTB + kb); // fj2, fj3
#pragma unroll
            for (int fi = 0; fi < 4; ++fi)
                LDSM_X4(af[fi], a_base + fi * 16 * SSTB + kb);
#pragma unroll
            for (int fi = 0; fi < 4; ++fi) {
                mma_s8(acc[fi][0][0], acc[fi][0][1], acc[fi][0][2], acc[fi][0][3],
                       af[fi][0], af[fi][1], af[fi][2], af[fi][3], bf0[0], bf0[1]);
                mma_s8(acc[fi][1][0], acc[fi][1][1], acc[fi][1][2], acc[fi][1][3],
                       af[fi][0], af[fi][1], af[fi][2], af[fi][3], bf0[2], bf0[3]);
                mma_s8(acc[fi][2][0], acc[fi][2][1], acc[fi][2][2], acc[fi][2][3],
                       af[fi][0], af[fi][1], af[fi][2], af[fi][3], bf1[0], bf1[1]);
                mma_s8(acc[fi][3][0], acc[fi][3][1], acc[fi][3][2], acc[fi][3][3],
                       af[fi][0], af[fi][1], af[fi][2], af[fi][3], bf1[2], bf1[3]);
            }
        }
    };

    cp_wait<3>(); __syncthreads(); compute_stage(0);
    cp_wait<2>(); __syncthreads(); compute_stage(1);
    cp_wait<1>(); __syncthreads(); compute_stage(2);
    cp_wait<0>(); __syncthreads(); compute_stage(3);

    // ---- epilogue ----
    __syncthreads();
    float* sxx = (float*)smem;          // 256
    float* syy = sxx + 256;             // 128
    float* ssx = syy + 128;             // 256  (2*scale_x)
    float* ssy = ssx + 256;             // 128  (scale_y)
    if (tid < 256) {
        sxx[tid] = g_xx[b * NPTS + n0 + tid];
        ssx[tid] = 2.0f * g_sx[b * NPTS + n0 + tid];
    } else if (tid < 384) {
        syy[tid - 256] = g_yy[b * NPTS + m0 + (tid - 256)];
        ssy[tid - 256] = g_sy[b * NPTS + m0 + (tid - 256)];
    }
    __syncthreads();

    const float INF = 3.402823466e38f;
    float rmin[8], cmin[8];
#pragma unroll
    for (int i = 0; i < 8; ++i) { rmin[i] = INF; cmin[i] = INF; }

    float xr[8], kx[8], yc[8], ky[8];
#pragma unroll
    for (int fi = 0; fi < 4; ++fi) {
        int r0 = wn * 64 + fi * 16 + r4;
        xr[fi * 2 + 0] = sxx[r0];      kx[fi * 2 + 0] = ssx[r0];
        xr[fi * 2 + 1] = sxx[r0 + 8];  kx[fi * 2 + 1] = ssx[r0 + 8];
    }
#pragma unroll
    for (int fj = 0; fj < 4; ++fj) {
        int c0 = wm * 32 + fj * 8 + 2 * c4;
        yc[fj * 2 + 0] = syy[c0];      ky[fj * 2 + 0] = ssy[c0];
        yc[fj * 2 + 1] = syy[c0 + 1];  ky[fj * 2 + 1] = ssy[c0 + 1];
    }

#pragma unroll
    for (int fi = 0; fi < 4; ++fi)
#pragma unroll
        for (int fj = 0; fj < 4; ++fj)
#pragma unroll
            for (int r = 0; r < 2; ++r)
#pragma unroll
                for (int c = 0; c < 2; ++c) {
                    float f = (float)acc[fi][fj][2 * r + c];
                    float d = xr[fi * 2 + r] + yc[fj * 2 + c]
                            - kx[fi * 2 + r] * ky[fj * 2 + c] * f;
                    rmin[fi * 2 + r] = fminf(rmin[fi * 2 + r], d);
                    cmin[fj * 2 + c] = fminf(cmin[fj * 2 + c], d);
                }

    // row mins: reduce across quad lanes (c4)
#pragma unroll
    for (int i = 0; i < 8; ++i) {
        rmin[i] = fminf(rmin[i], __shfl_xor_sync(0xFFFFFFFFu, rmin[i], 1));
        rmin[i] = fminf(rmin[i], __shfl_xor_sync(0xFFFFFFFFu, rmin[i], 2));
    }
    if (c4 == 0) {
#pragma unroll
        for (int fi = 0; fi < 4; ++fi)
#pragma unroll
            for (int r = 0; r < 2; ++r) {
                int row = n0 + wn * 64 + fi * 16 + 8 * r + r4;
                atomicMin(&g_min_n[b * NPTS + row], f2ord(rmin[fi * 2 + r]));
            }
    }

    // col mins: reduce across r4 lanes
#pragma unroll
    for (int i = 0; i < 8; ++i) {
        cmin[i] = fminf(cmin[i], __shfl_xor_sync(0xFFFFFFFFu, cmin[i], 4));
        cmin[i] = fminf(cmin[i], __shfl_xor_sync(0xFFFFFFFFu, cmin[i], 8));
        cmin[i] = fminf(cmin[i], __shfl_xor_sync(0xFFFFFFFFu, cmin[i], 16));
    }
    if (r4 == 0) {
#pragma unroll
        for (int fj = 0; fj < 4; ++fj)
#pragma unroll
            for (int c = 0; c < 2; ++c) {
                int col = m0 + wm * 32 + fj * 8 + 2 * c4 + c;
                atomicMin(&g_min_m[b * NPTS + col], f2ord(cmin[fj * 2 + c]));
            }
    }
}

// ---------------------------------------------------------------------------
// Kernel 3: sum mins -> scalar
// ---------------------------------------------------------------------------
__global__ void finalize_kernel(float* __restrict__ out) {
    __shared__ double sm[1024];
    const int tid = threadIdx.x;
    const int total = BATCH * NPTS;
    double s = 0.0;
    for (int i = tid; i < total; i += 1024) s += (double)ord2f(g_min_n[i]);
    for (int i = tid; i < total; i += 1024) s += (double)ord2f(g_min_m[i]);
    sm[tid] = s;
    __syncthreads();
    for (int off = 512; off > 0; off >>= 1) {
        if (tid < off) sm[tid] += sm[tid + off];
        __syncthreads();
    }
    if (tid == 0) out[0] = (float)sm[0];
}

extern "C" void kernel_launch(void* const* d_in, const int* in_sizes, int n_in,
                              void* d_out, int out_size) {
    const float* gts   = (const float*)d_in[0];
    const float* preds = (const float*)d_in[1];
    float* out = (float*)d_out;

    static int attr_set = 0;
    if (!attr_set) {
        cudaFuncSetAttribute(chamfer_mma_kernel,
                             cudaFuncAttributeMaxDynamicSharedMemorySize, SMEM_BYTES);
        attr_set = 1;
    }

    dim3 gN((BATCH * NPTS) / 8, 2);
    norms_init_kernel<<<gN, 256>>>(gts, preds);

    dim3 gT(NPTS / TILE_M, NPTS / TILE_N, BATCH);
    chamfer_mma_kernel<<<gT, 512, SMEM_BYTES>>>();

    finalize_kernel<<<1, 1024>>>(out);
}

// round 10
// speedup vs baseline: 2.1634x; 2.1634x over previous
#include <cuda_runtime.h>
#include <cuda_bf16.h>
#include <cuda_fp16.h>
#include <cstdint>

#define BATCH 8
#define NPTS  4096
#define DIM   256

// tile geometry
#define TILE_N 256            // X rows per CTA (gemm M)
#define TILE_M 128            // Y rows per m-tile (gemm N)
#define MT     4              // m-tiles per CTA
#define KCH    32             // K fp16 elements per stage
#define NSTG   8              // DIM / KCH
#define TOTSTG (MT * NSTG)    // 32
#define SST    40             // smem row stride in fp16 (80B rows; ldmatrix conflict-free)

#define A_HALFS (TILE_N * SST)             // 10240
#define B_HALFS (TILE_M * SST)             // 5120
#define STAGE_HALFS (A_HALFS + B_HALFS)    // 15360
#define STAGE_BYTES (STAGE_HALFS * 2)      // 30720
#define SMEM_BYTES  (4 * STAGE_BYTES)      // 122880

// ---------------- scratch globals ----------------
__device__ unsigned g_min_n[BATCH * NPTS];
__device__ unsigned g_min_m[BATCH * NPTS];
__device__ float    g_xx[BATCH * NPTS];
__device__ float    g_yy[BATCH * NPTS];
__device__ __half   g_xh[BATCH * NPTS * DIM];   // 16 MB
__device__ __half   g_yh[BATCH * NPTS * DIM];   // 16 MB

__device__ __forceinline__ unsigned f2ord(float f) {
    unsigned u = __float_as_uint(f);
    return (u & 0x80000000u) ? ~u : (u ^ 0x80000000u);
}
__device__ __forceinline__ float ord2f(unsigned u) {
    u = (u & 0x80000000u) ? (u ^ 0x80000000u) : ~u;
    return __uint_as_float(u);
}

__device__ __forceinline__ uint32_t smem_u32(const void* p) {
    uint32_t a;
    asm("{ .reg .u64 t; cvta.to.shared.u64 t, %1; cvt.u32.u64 %0, t; }" : "=r"(a) : "l"(p));
    return a;
}
__device__ __forceinline__ void cpasync16(uint32_t dst, const void* src) {
    asm volatile("cp.async.cg.shared.global [%0], [%1], 16;" :: "r"(dst), "l"(src));
}
#define CP_COMMIT() asm volatile("cp.async.commit_group;" ::: "memory")
#define CP_WAIT2()  asm volatile("cp.async.wait_group 2;" ::: "memory")

#define LDSM_X4(r, a) \
    asm volatile("ldmatrix.sync.aligned.m8n8.x4.shared.b16 {%0,%1,%2,%3}, [%4];" \
        : "=r"((r)[0]), "=r"((r)[1]), "=r"((r)[2]), "=r"((r)[3]) : "r"(a))

__device__ __forceinline__ void mma_f16(float& d0, float& d1, float& d2, float& d3,
                                        uint32_t a0, uint32_t a1, uint32_t a2, uint32_t a3,
                                        uint32_t b0, uint32_t b1) {
    asm volatile(
        "mma.sync.aligned.m16n8k16.row.col.f32.f16.f16.f32 "
        "{%0,%1,%2,%3}, {%4,%5,%6,%7}, {%8,%9}, {%0,%1,%2,%3};"
        : "+f"(d0), "+f"(d1), "+f"(d2), "+f"(d3)
        : "r"(a0), "r"(a1), "r"(a2), "r"(a3), "r"(b0), "r"(b1));
}

// ---------------------------------------------------------------------------
// Kernel 1: row norms + min init + fp32 -> fp16 conversion (one warp per row)
// ---------------------------------------------------------------------------
__global__ void norms_init_kernel(const float* __restrict__ X,
                                  const float* __restrict__ Y) {
    int warp = (blockIdx.x * blockDim.x + threadIdx.x) >> 5;
    int lane = threadIdx.x & 31;
    const float* src = (blockIdx.y == 0) ? X : Y;
    float*    dst_n  = (blockIdx.y == 0) ? g_xx : g_yy;
    unsigned* dst_mn = (blockIdx.y == 0) ? g_min_n : g_min_m;
    __half*   dst_h  = (blockIdx.y == 0) ? g_xh : g_yh;

    const float4* row = (const float4*)(src + (size_t)warp * DIM);
    float4 a = row[lane];
    float4 b = row[lane + 32];

    __half2* hrow = (__half2*)(dst_h + (size_t)warp * DIM);
    hrow[lane * 2 + 0]      = __floats2half2_rn(a.x, a.y);
    hrow[lane * 2 + 1]      = __floats2half2_rn(a.z, a.w);
    hrow[64 + lane * 2 + 0] = __floats2half2_rn(b.x, b.y);
    hrow[64 + lane * 2 + 1] = __floats2half2_rn(b.z, b.w);

    float s = a.x * a.x + a.y * a.y + a.z * a.z + a.w * a.w
            + b.x * b.x + b.y * b.y + b.z * b.z + b.w * b.w;
#pragma unroll
    for (int off = 16; off > 0; off >>= 1)
        s += __shfl_xor_sync(0xFFFFFFFFu, s, off);
    if (lane == 0) {
        dst_n[warp]  = s;
        dst_mn[warp] = 0xFFFFFFFFu;
    }
}

// ---------------------------------------------------------------------------
// Kernel 2: fp16 mma.sync + ldmatrix. CTA = 256(n) x 4 tiles of 128(m).
// grid: (NPTS/(TILE_M*MT), NPTS/TILE_N, BATCH), 512 threads
// ---------------------------------------------------------------------------
__global__ __launch_bounds__(512, 1)
void chamfer_mma_kernel() {
    extern __shared__ __align__(16) char smem[];
    const uint32_t sb = smem_u32(smem);

    const int tid  = threadIdx.x;
    const int wid  = tid >> 5;
    const int lane = tid & 31;
    const int r4   = lane >> 2;   // 0..7
    const int c4   = lane & 3;    // 0..3
    const int wn   = wid >> 2;    // warp n-group: 64 rows
    const int wm   = wid & 3;     // warp m-group: 32 cols

    const int b     = blockIdx.z;
    const int n0    = blockIdx.y * TILE_N;
    const int m0bas = blockIdx.x * (TILE_M * MT);

    const __half* xb = g_xh + ((size_t)b * NPTS + n0) * DIM;
    const __half* yb = g_yh + ((size_t)b * NPTS + m0bas) * DIM;

    // per-lane ldmatrix base offsets (bytes within a stage buffer)
    const uint32_t a_off = (uint32_t)(((wn * 64 + (lane & 15)) * SST
                                       + ((lane >> 4) & 1) * 8) * 2);
    const uint32_t b_off = (uint32_t)(A_HALFS * 2
                         + ((wm * 32 + (lane >> 4) * 8 + (lane & 7)) * SST
                            + ((lane >> 3) & 1) * 8) * 2);

    // ---- async load of global stage g (tile g/NSTG, k-chunk g%NSTG) ----
    auto load_stage = [&](int g) {
        const uint32_t base = sb + (g & 3) * STAGE_BYTES;
        const int t    = g >> 3;          // m-tile
        const int koff = (g & 7) * KCH;
        const __half* ybt = yb + (size_t)t * TILE_M * DIM;
#pragma unroll
        for (int i = 0; i < 2; ++i) {
            int cid = tid + i * 512;
            int row = cid >> 2, k8 = cid & 3;
            cpasync16(base + (uint32_t)(row * 80 + k8 * 16),
                      xb + (size_t)row * DIM + koff + k8 * 8);
        }
        {
            int row = tid >> 2, k8 = tid & 3;
            cpasync16(base + (uint32_t)(A_HALFS * 2 + row * 80 + k8 * 16),
                      ybt + (size_t)row * DIM + koff + k8 * 8);
        }
    };

    load_stage(0); CP_COMMIT();
    load_stage(1); CP_COMMIT();
    load_stage(2); CP_COMMIT();

    float acc[4][4][4];
#pragma unroll
    for (int fi = 0; fi < 4; ++fi)
#pragma unroll
        for (int fj = 0; fj < 4; ++fj)
#pragma unroll
            for (int q = 0; q < 4; ++q) acc[fi][fj][q] = 0.f;

    // persistent row state (rows fixed across all m-tiles)
    const float INF = 3.402823466e38f;
    float rmin[8], xr[8];
#pragma unroll
    for (int i = 0; i < 8; ++i) rmin[i] = INF;
#pragma unroll
    for (int fi = 0; fi < 4; ++fi) {
        int r0 = b * NPTS + n0 + wn * 64 + fi * 16 + r4;
        xr[fi * 2 + 0] = g_xx[r0];
        xr[fi * 2 + 1] = g_xx[r0 + 8];
    }

#pragma unroll 1
    for (int g = 0; g < TOTSTG; ++g) {
        CP_WAIT2();
        __syncthreads();

        const uint32_t stage  = sb + (g & 3) * STAGE_BYTES;
        const uint32_t a_base = stage + a_off;
        const uint32_t b_base = stage + b_off;

#pragma unroll
        for (int k16 = 0; k16 < 2; ++k16) {
            const uint32_t kb = k16 * 32;
            uint32_t af[4][4], bf0[4], bf1[4];
            LDSM_X4(bf0, b_base + kb);
            LDSM_X4(bf1, b_base + 16 * SST * 2 + kb);
#pragma unroll
            for (int fi = 0; fi < 4; ++fi)
                LDSM_X4(af[fi], a_base + fi * 16 * SST * 2 + kb);
#pragma unroll
            for (int fi = 0; fi < 4; ++fi) {
                mma_f16(acc[fi][0][0], acc[fi][0][1], acc[fi][0][2], acc[fi][0][3],
                        af[fi][0], af[fi][1], af[fi][2], af[fi][3], bf0[0], bf0[1]);
                mma_f16(acc[fi][1][0], acc[fi][1][1], acc[fi][1][2], acc[fi][1][3],
                        af[fi][0], af[fi][1], af[fi][2], af[fi][3], bf0[2], bf0[3]);
                mma_f16(acc[fi][2][0], acc[fi][2][1], acc[fi][2][2], acc[fi][2][3],
                        af[fi][0], af[fi][1], af[fi][2], af[fi][3], bf1[0], bf1[1]);
                mma_f16(acc[fi][3][0], acc[fi][3][1], acc[fi][3][2], acc[fi][3][3],
                        af[fi][0], af[fi][1], af[fi][2], af[fi][3], bf1[2], bf1[3]);
            }
        }

        if (g + 3 < TOTSTG) load_stage(g + 3);
        CP_COMMIT();

        // ---- per-tile epilogue (smem-free; overlaps in-flight cp.async) ----
        if ((g & 7) == 7) {
            const int t   = g >> 3;
            const int m0t = m0bas + t * TILE_M;

            float yc[8];
#pragma unroll
            for (int fj = 0; fj < 4; ++fj) {
                int c0 = b * NPTS + m0t + wm * 32 + fj * 8 + 2 * c4;
                yc[fj * 2 + 0] = g_yy[c0];
                yc[fj * 2 + 1] = g_yy[c0 + 1];
            }

            float cmin[8];
#pragma unroll
            for (int i = 0; i < 8; ++i) cmin[i] = INF;

#pragma unroll
            for (int fi = 0; fi < 4; ++fi)
#pragma unroll
                for (int fj = 0; fj < 4; ++fj)
#pragma unroll
                    for (int r = 0; r < 2; ++r)
#pragma unroll
                        for (int c = 0; c < 2; ++c) {
                            float d = xr[fi * 2 + r] + yc[fj * 2 + c]
                                    - 2.0f * acc[fi][fj][2 * r + c];
                            rmin[fi * 2 + r] = fminf(rmin[fi * 2 + r], d);
                            cmin[fj * 2 + c] = fminf(cmin[fj * 2 + c], d);
                            acc[fi][fj][2 * r + c] = 0.f;
                        }

            // col mins: reduce across r4 lanes, flush to global
#pragma unroll
            for (int i = 0; i < 8; ++i) {
                cmin[i] = fminf(cmin[i], __shfl_xor_sync(0xFFFFFFFFu, cmin[i], 4));
                cmin[i] = fminf(cmin[i], __shfl_xor_sync(0xFFFFFFFFu, cmin[i], 8));
                cmin[i] = fminf(cmin[i], __shfl_xor_sync(0xFFFFFFFFu, cmin[i], 16));
            }
            if (r4 == 0) {
#pragma unroll
                for (int fj = 0; fj < 4; ++fj)
#pragma unroll
                    for (int c = 0; c < 2; ++c) {
                        int col = m0t + wm * 32 + fj * 8 + 2 * c4 + c;
                        atomicMin(&g_min_m[b * NPTS + col], f2ord(cmin[fj * 2 + c]));
                    }
            }
        }
    }

    // ---- final row-min flush (accumulated over all MT tiles) ----
#pragma unroll
    for (int i = 0; i < 8; ++i) {
        rmin[i] = fminf(rmin[i], __shfl_xor_sync(0xFFFFFFFFu, rmin[i], 1));
        rmin[i] = fminf(rmin[i], __shfl_xor_sync(0xFFFFFFFFu, rmin[i], 2));
    }
    if (c4 == 0) {
#pragma unroll
        for (int fi = 0; fi < 4; ++fi)
#pragma unroll
            for (int r = 0; r < 2; ++r) {
                int row = n0 + wn * 64 + fi * 16 + 8 * r + r4;
                atomicMin(&g_min_n[b * NPTS + row], f2ord(rmin[fi * 2 + r]));
            }
    }
}

// ---------------------------------------------------------------------------
// Kernel 3: sum mins -> scalar
// ---------------------------------------------------------------------------
__global__ void finalize_kernel(float* __restrict__ out) {
    __shared__ double sm[1024];
    const int tid = threadIdx.x;
    const int total = BATCH * NPTS;
    double s = 0.0;
    for (int i = tid; i < total; i += 1024) s += (double)ord2f(g_min_n[i]);
    for (int i = tid; i < total; i += 1024) s += (double)ord2f(g_min_m[i]);
    sm[tid] = s;
    __syncthreads();
    for (int off = 512; off > 0; off >>= 1) {
        if (tid < off) sm[tid] += sm[tid + off];
        __syncthreads();
    }
    if (tid == 0) out[0] = (float)sm[0];
}

extern "C" void kernel_launch(void* const* d_in, const int* in_sizes, int n_in,
                              void* d_out, int out_size) {
    const float* gts   = (const float*)d_in[0];
    const float* preds = (const float*)d_in[1];
    float* out = (float*)d_out;

    cudaFuncSetAttribute(chamfer_mma_kernel,
                         cudaFuncAttributeMaxDynamicSharedMemorySize, SMEM_BYTES);

    dim3 gN((BATCH * NPTS) / 8, 2);
    norms_init_kernel<<<gN, 256>>>(gts, preds);

    dim3 gT(NPTS / (TILE_M * MT), NPTS / TILE_N, BATCH);
    chamfer_mma_kernel<<<gT, 512, SMEM_BYTES>>>();

    finalize_kernel<<<1, 1024>>>(out);
}